// round 16
// baseline (speedup 1.0000x reference)
#include <cuda_runtime.h>
#include <cuda_bf16.h>
#include <cstdint>
#include <math.h>

#define N_    64
#define C_    128
#define K_    64
#define P_    4096
#define ALPHA_ 50.0f
#define EPS_  1e-12f

typedef unsigned long long ull;
typedef unsigned int uint32;

// ---------------- scratch ----------------
__device__ float g_partial[N_ * 4 * K_ * C_];   // [n][ps][k][c]
__device__ float g_sasum[N_ * 4 * K_];          // [n][ps][k]

// ---------------- helpers ----------------
__device__ __forceinline__ uint32 smem_u32(const void* p) {
    uint32 a;
    asm("{ .reg .u64 t; cvta.to.shared.u64 t, %1; cvt.u32.u64 %0, t; }" : "=r"(a) : "l"(p));
    return a;
}
__device__ __forceinline__ void ldmat_x4(uint32& r0, uint32& r1, uint32& r2, uint32& r3, uint32 addr) {
    asm volatile("ldmatrix.sync.aligned.m8n8.x4.shared.b16 {%0,%1,%2,%3}, [%4];"
                 : "=r"(r0), "=r"(r1), "=r"(r2), "=r"(r3) : "r"(addr));
}
__device__ __forceinline__ void ldmat_x4t(uint32& r0, uint32& r1, uint32& r2, uint32& r3, uint32 addr) {
    asm volatile("ldmatrix.sync.aligned.m8n8.x4.trans.shared.b16 {%0,%1,%2,%3}, [%4];"
                 : "=r"(r0), "=r"(r1), "=r"(r2), "=r"(r3) : "r"(addr));
}
__device__ __forceinline__ void mma16816(float& d0, float& d1, float& d2, float& d3,
                                         uint32 a0, uint32 a1, uint32 a2, uint32 a3,
                                         uint32 b0, uint32 b1) {
    asm volatile("mma.sync.aligned.m16n8k16.row.col.f32.bf16.bf16.f32 "
                 "{%0,%1,%2,%3}, {%4,%5,%6,%7}, {%8,%9}, {%0,%1,%2,%3};"
                 : "+f"(d0), "+f"(d1), "+f"(d2), "+f"(d3)
                 : "r"(a0), "r"(a1), "r"(a2), "r"(a3), "r"(b0), "r"(b1));
}
__device__ __forceinline__ uint32 pack_bf16x2(float lo, float hi) {
    __nv_bfloat16 a = __float2bfloat16(lo), b = __float2bfloat16(hi);
    return (uint32)__bfloat16_as_ushort(a) | ((uint32)__bfloat16_as_ushort(b) << 16);
}
__device__ __forceinline__ void split_hl(float v, float& h, float& l) {
    __nv_bfloat16 hb = __float2bfloat16(v);
    h = __bfloat162float(hb);
    l = v - h;
}
// fast packed split: hw = {bf16(v1),bf16(v0)}, lw = residuals (cvt.rn everywhere)
__device__ __forceinline__ void cvt_pair(float v0, float v1, uint32& hw, uint32& lw) {
    asm("cvt.rn.bf16x2.f32 %0, %1, %2;" : "=r"(hw) : "f"(v1), "f"(v0));
    float h0 = __uint_as_float(hw << 16);
    float h1 = __uint_as_float(hw & 0xFFFF0000u);
    float l0 = v0 - h0, l1 = v1 - h1;
    asm("cvt.rn.bf16x2.f32 %0, %1, %2;" : "=r"(lw) : "f"(l1), "f"(l0));
}

// ---------------- smem layout (bytes) ----------------
#define SM_WNTH 0                 // WnT bf16 hi [64 k][128 c] rows 272B  17408
#define SM_WNTL 17408             // WnT bf16 lo                          17408
#define SM_XAH  34816             // x bf16 hi [128 c][64 p] rows 144B    18432
#define SM_XAL  53248             // x bf16 lo                            18432
#define SM_S    71680             // sas fp32 [64][68]                    17408
#define SM_SAH  89088             // sa bf16 hi [64 k][64 p] rows 144B     9216
#define SM_SAL  98304             // sa bf16 lo                            9216
#define SM_BS   107520
#define SM_INV  107776
#define SM_TOT  108032

#define SFS  68      // fp32 sas stride (floats)
#define BROW 144     // x/sa bf16 row stride (bytes)
#define WROW 272     // WnT bf16 row stride (bytes)

// ---------------- fused mega kernel: grid (4, 64), 256 threads ----------------
__global__ __launch_bounds__(256, 2) void kMega(const float* __restrict__ x,
                                                const float* __restrict__ W,
                                                const float* __restrict__ bias,
                                                float* __restrict__ logits_out) {
    extern __shared__ char smc[];
    float* sas  = (float*)(smc + SM_S);
    float* bs   = (float*)(smc + SM_BS);
    float* invv = (float*)(smc + SM_INV);

    const int tid = threadIdx.x;
    const int wid = tid >> 5;
    const int lane = tid & 31;
    const int n   = blockIdx.y;
    const int ps  = blockIdx.x;              // 0..3, 1024 px

    const uint32 sbase = smem_u32(smc);

    // ==== prologue: build WnT bf16 hi/lo [k][c] ====
    {
        float* wtmp = (float*)(smc + SM_XAH);   // fp32 [c][k] scratch (32KB)
        for (int i = tid; i < C_ * K_; i += 256) wtmp[i] = W[i];
        if (tid < 64) bs[tid] = bias[tid];
        __syncthreads();
        {
            const int kk = tid & 63, q = tid >> 6;
            float ss = 0.f;
            #pragma unroll 8
            for (int c = q * 32; c < q * 32 + 32; ++c) {
                float v = wtmp[c * K_ + kk];
                ss = fmaf(v, v, ss);
            }
            sas[q * 64 + kk] = ss;
        }
        __syncthreads();
        if (tid < 64) {
            float tot = sas[tid] + sas[64 + tid] + sas[128 + tid] + sas[192 + tid];
            sas[512 + tid] = 1.f / fmaxf(sqrtf(tot), EPS_);
        }
        __syncthreads();
        {
            const int kk = tid & 63, q = tid >> 6;
            float ik = sas[512 + kk];
            #pragma unroll
            for (int j = 0; j < 16; ++j) {
                int c0 = q * 32 + 2 * j;
                float v0 = wtmp[c0 * K_ + kk] * ik;
                float v1 = wtmp[(c0 + 1) * K_ + kk] * ik;
                float h0, l0, h1, l1;
                split_hl(v0, h0, l0);
                split_hl(v1, h1, l1);
                *(uint32*)(smc + SM_WNTH + kk * WROW + c0 * 2) = pack_bf16x2(h0, h1);
                *(uint32*)(smc + SM_WNTL + kk * WROW + c0 * 2) = pack_bf16x2(l0, l1);
            }
        }
        __syncthreads();
    }

    // role mappings
    const int pq = tid & 15, cq = tid >> 4;    // loader
    const int pN = tid >> 2, qN = tid & 3;     // softmax
    const int kS = tid & 63, part = tid >> 6;  // sa convert/sasum

    float acc[8][4];                           // GEMM2 accum (persistent)
    #pragma unroll
    for (int a = 0; a < 8; ++a)
        #pragma unroll
        for (int b = 0; b < 4; ++b) acc[a][b] = 0.f;
    float sasum_reg = 0.f;

    const float* xbase = x + (size_t)n * C_ * P_ + ps * 1024;
    float* lb = logits_out + (size_t)n * K_ * P_ + ps * 1024;

    const int k0w = (wid & 3) * 16;            // GEMM1 warp tile
    const int phalf = (wid >> 2) * 32;

    // ---- prefetch subtile 0 into registers ----
    float4 pv[8];
    {
        const float* xp = xbase + pq * 4;
        #pragma unroll
        for (int i = 0; i < 8; ++i)
            pv[i] = *(const float4*)(xp + (size_t)(cq + 16 * i) * P_);
    }

    for (int sub = 0; sub < 16; ++sub) {
        const int p0 = sub * 64;

        // ---- A: consume prefetched x -> bf16 hi/lo [c][p] + sumsq ----
        {
            float s0 = 0.f, s1 = 0.f, s2 = 0.f, s3 = 0.f;
            #pragma unroll
            for (int i = 0; i < 8; ++i) {
                int c = cq + 16 * i;
                float4 v = pv[i];
                s0 = fmaf(v.x, v.x, s0);
                s1 = fmaf(v.y, v.y, s1);
                s2 = fmaf(v.z, v.z, s2);
                s3 = fmaf(v.w, v.w, s3);
                uint2 hv, lv;
                cvt_pair(v.x, v.y, hv.x, lv.x);
                cvt_pair(v.z, v.w, hv.y, lv.y);
                *(uint2*)(smc + SM_XAH + c * BROW + pq * 8) = hv;
                *(uint2*)(smc + SM_XAL + c * BROW + pq * 8) = lv;
            }
            *(float4*)(sas + cq * 64 + pq * 4) = make_float4(s0, s1, s2, s3);
        }
        // ---- issue prefetch for next subtile (overlaps GEMM1..GEMM2) ----
        if (sub < 15) {
            const float* xp = xbase + (sub + 1) * 64 + pq * 4;
            #pragma unroll
            for (int i = 0; i < 8; ++i)
                pv[i] = *(const float4*)(xp + (size_t)(cq + 16 * i) * P_);
        }
        __syncthreads();   // (1)

        // ---- B: invn (tid<64) || GEMM1 tensor: D[k][p] = Wn^T x ----
        if (tid < 64) {
            float tot = 0.f;
            #pragma unroll
            for (int q = 0; q < 16; ++q) tot += sas[q * 64 + tid];
            invv[tid] = 1.f / fmaxf(sqrtf(tot), EPS_);
        }
        float f1[4][4];
        #pragma unroll
        for (int a = 0; a < 4; ++a)
            #pragma unroll
            for (int b = 0; b < 4; ++b) f1[a][b] = 0.f;
        {
            uint32 aH = sbase + SM_WNTH + (k0w + (lane & 15)) * WROW + (lane >> 4) * 16;
            uint32 aL = aH + (SM_WNTL - SM_WNTH);
            uint32 bB = sbase + SM_XAH + lane * BROW + phalf * 2;
            #pragma unroll
            for (int kcp = 0; kcp < 4; ++kcp) {
                uint32 AhA0, AhA1, AhA2, AhA3, AhB0, AhB1, AhB2, AhB3;
                uint32 AlA0, AlA1, AlA2, AlA3, AlB0, AlB1, AlB2, AlB3;
                ldmat_x4(AhA0, AhA1, AhA2, AhA3, aH + (2 * kcp) * 32);
                ldmat_x4(AhB0, AhB1, AhB2, AhB3, aH + (2 * kcp + 1) * 32);
                ldmat_x4(AlA0, AlA1, AlA2, AlA3, aL + (2 * kcp) * 32);
                ldmat_x4(AlB0, AlB1, AlB2, AlB3, aL + (2 * kcp + 1) * 32);
                #pragma unroll
                for (int nt = 0; nt < 4; ++nt) {
                    uint32 Bh0, Bh1, Bh2, Bh3, Bl0, Bl1, Bl2, Bl3;
                    uint32 ba = bB + kcp * 32 * BROW + nt * 16;
                    ldmat_x4t(Bh0, Bh1, Bh2, Bh3, ba);
                    ldmat_x4t(Bl0, Bl1, Bl2, Bl3, ba + (SM_XAL - SM_XAH));
                    mma16816(f1[nt][0], f1[nt][1], f1[nt][2], f1[nt][3],
                             AhA0, AhA1, AhA2, AhA3, Bh0, Bh1);
                    mma16816(f1[nt][0], f1[nt][1], f1[nt][2], f1[nt][3],
                             AhA0, AhA1, AhA2, AhA3, Bl0, Bl1);
                    mma16816(f1[nt][0], f1[nt][1], f1[nt][2], f1[nt][3],
                             AlA0, AlA1, AlA2, AlA3, Bh0, Bh1);
                    mma16816(f1[nt][0], f1[nt][1], f1[nt][2], f1[nt][3],
                             AhB0, AhB1, AhB2, AhB3, Bh2, Bh3);
                    mma16816(f1[nt][0], f1[nt][1], f1[nt][2], f1[nt][3],
                             AhB0, AhB1, AhB2, AhB3, Bl2, Bl3);
                    mma16816(f1[nt][0], f1[nt][1], f1[nt][2], f1[nt][3],
                             AlB0, AlB1, AlB2, AlB3, Bh2, Bh3);
                }
            }
        }
        __syncthreads();   // (2) invv ready; sas scratch free

        // ---- C: epilogue: x invn -> sas fp32 [k][p] AND logits -> gmem ----
        {
            const int r0 = k0w + (lane >> 2);
            #pragma unroll
            for (int nt = 0; nt < 4; ++nt) {
                int pc = phalf + nt * 8 + 2 * (lane & 3);
                float i0 = invv[pc], i1 = invv[pc + 1];
                float2 lo = make_float2(f1[nt][0] * i0, f1[nt][1] * i1);
                float2 hi = make_float2(f1[nt][2] * i0, f1[nt][3] * i1);
                *(float2*)(sas + r0 * SFS + pc)       = lo;
                *(float2*)(sas + (r0 + 8) * SFS + pc) = hi;
                *(float2*)(lb + (size_t)r0 * P_ + p0 + pc)       = lo;
                *(float2*)(lb + (size_t)(r0 + 8) * P_ + p0 + pc) = hi;
            }
        }
        __syncthreads();   // (3)

        // ---- E: softmax over k per pixel (4 thr/pixel), in place ----
        {
            float lv[16];
            float m = -3.4e38f;
            #pragma unroll
            for (int i = 0; i < 16; ++i) {
                int k = qN + 4 * i;
                float t = (sas[k * SFS + pN] + bs[k]) * ALPHA_;
                lv[i] = t; m = fmaxf(m, t);
            }
            m = fmaxf(m, __shfl_xor_sync(0xffffffffu, m, 1));
            m = fmaxf(m, __shfl_xor_sync(0xffffffffu, m, 2));
            float s = 0.f;
            #pragma unroll
            for (int i = 0; i < 16; ++i) {
                float e = __expf(lv[i] - m);
                lv[i] = e; s += e;
            }
            s += __shfl_xor_sync(0xffffffffu, s, 1);
            s += __shfl_xor_sync(0xffffffffu, s, 2);
            float rs = 1.f / s;
            #pragma unroll
            for (int i = 0; i < 16; ++i)
                sas[(qN + 4 * i) * SFS + pN] = lv[i] * rs;
        }
        __syncthreads();   // (4)

        // ---- F: sa fp32 -> sasum + bf16 hi/lo (x invn) ----
        {
            float sv[16];
            #pragma unroll
            for (int j = 0; j < 4; ++j) {
                float4 v = *(const float4*)(sas + kS * SFS + part * 16 + j * 4);
                sv[j * 4 + 0] = v.x; sv[j * 4 + 1] = v.y;
                sv[j * 4 + 2] = v.z; sv[j * 4 + 3] = v.w;
            }
            #pragma unroll
            for (int j = 0; j < 16; ++j) sasum_reg += sv[j];

            uint32 hw[8], lw[8];
            #pragma unroll
            for (int j = 0; j < 8; ++j) {
                // fold invn: GEMM2 x-tile is RAW x, so sa carries invn[p]
                float v0 = sv[2 * j]     * invv[part * 16 + 2 * j];
                float v1 = sv[2 * j + 1] * invv[part * 16 + 2 * j + 1];
                cvt_pair(v0, v1, hw[j], lw[j]);
            }
            char* dh = smc + SM_SAH + kS * BROW + part * 32;
            char* dl = smc + SM_SAL + kS * BROW + part * 32;
            *(uint4*)dh        = make_uint4(hw[0], hw[1], hw[2], hw[3]);
            *(uint4*)(dh + 16) = make_uint4(hw[4], hw[5], hw[6], hw[7]);
            *(uint4*)dl        = make_uint4(lw[0], lw[1], lw[2], lw[3]);
            *(uint4*)(dl + 16) = make_uint4(lw[4], lw[5], lw[6], lw[7]);
        }
        __syncthreads();   // (5) bf16 sa ready

        // ---- G: GEMM2 tensor: D[c][k] += x sa^T (contraction p) ----
        {
            const int c0 = wid * 16;
            const int ar = lane & 15, ah = lane >> 4;
            uint32 aAddrH = sbase + SM_XAH + (c0 + ar) * BROW + ah * 16;
            uint32 aAddrL = sbase + SM_XAL + (c0 + ar) * BROW + ah * 16;
            uint32 bRow = (lane >> 4) * 8 + (lane & 7);
            uint32 bHalf = ((lane >> 3) & 1) * 16;
            #pragma unroll
            for (int kc = 0; kc < 4; ++kc) {
                uint32 Ah0, Ah1, Ah2, Ah3, Al0, Al1, Al2, Al3;
                ldmat_x4(Ah0, Ah1, Ah2, Ah3, aAddrH + kc * 32);
                ldmat_x4(Al0, Al1, Al2, Al3, aAddrL + kc * 32);
                #pragma unroll
                for (int ntp = 0; ntp < 4; ++ntp) {
                    uint32 Bh0, Bh1, Bh2, Bh3, Bl0, Bl1, Bl2, Bl3;
                    uint32 baH = sbase + SM_SAH + (ntp * 16 + bRow) * BROW + bHalf + kc * 32;
                    uint32 baL = baH + (SM_SAL - SM_SAH);
                    ldmat_x4(Bh0, Bh1, Bh2, Bh3, baH);
                    ldmat_x4(Bl0, Bl1, Bl2, Bl3, baL);
                    int ntA = 2 * ntp, ntB = 2 * ntp + 1;
                    mma16816(acc[ntA][0], acc[ntA][1], acc[ntA][2], acc[ntA][3],
                             Ah0, Ah1, Ah2, Ah3, Bh0, Bh1);
                    mma16816(acc[ntA][0], acc[ntA][1], acc[ntA][2], acc[ntA][3],
                             Ah0, Ah1, Ah2, Ah3, Bl0, Bl1);
                    mma16816(acc[ntA][0], acc[ntA][1], acc[ntA][2], acc[ntA][3],
                             Al0, Al1, Al2, Al3, Bh0, Bh1);
                    mma16816(acc[ntB][0], acc[ntB][1], acc[ntB][2], acc[ntB][3],
                             Ah0, Ah1, Ah2, Ah3, Bh2, Bh3);
                    mma16816(acc[ntB][0], acc[ntB][1], acc[ntB][2], acc[ntB][3],
                             Ah0, Ah1, Ah2, Ah3, Bl2, Bl3);
                    mma16816(acc[ntB][0], acc[ntB][1], acc[ntB][2], acc[ntB][3],
                             Al0, Al1, Al2, Al3, Bh2, Bh3);
                }
            }
        }
        __syncthreads();   // (6) mma reads done before next A overwrites
    }

    // ---- epilogue: write acc -> g_partial [k][c] ----
    {
        float* pp = g_partial + ((size_t)(n * 4 + ps) * K_) * C_;
        const int row = wid * 16 + (lane >> 2);
        const int col = 2 * (lane & 3);
        #pragma unroll
        for (int nt = 0; nt < 8; ++nt) {
            int k0 = nt * 8 + col;
            pp[(k0    ) * C_ + row    ] = acc[nt][0];
            pp[(k0 + 1) * C_ + row    ] = acc[nt][1];
            pp[(k0    ) * C_ + row + 8] = acc[nt][2];
            pp[(k0 + 1) * C_ + row + 8] = acc[nt][3];
        }
    }

    // ---- sasum reduce (sas free as fp32 scratch) ----
    sas[part * 64 + kS] = sasum_reg;
    __syncthreads();
    if (tid < 64)
        g_sasum[(n * 4 + ps) * 64 + tid] =
            sas[tid] + sas[64 + tid] + sas[128 + tid] + sas[192 + tid];
}

// ---------------- kernel D: combine + subtract + intra-norm + global/8 ----------------
__global__ __launch_bounds__(128) void kD(const float* __restrict__ W,
                                          float* __restrict__ vlad_out) {
    __shared__ float red[4];
    const int b = blockIdx.x;
    const int n = b >> 6, k = b & 63, tid = threadIdx.x;
    const int lane = tid & 31, w = tid >> 5;

    float sasum = 0.f;
    #pragma unroll
    for (int ps = 0; ps < 4; ++ps) sasum += g_sasum[(n * 4 + ps) * 64 + k];

    float v = 0.f;
    #pragma unroll
    for (int ps = 0; ps < 4; ++ps)
        v += g_partial[((size_t)(n * 4 + ps) * K_ + k) * C_ + tid];
    v = fmaf(-sasum, W[tid * K_ + k], v);

    float sq = v * v;
    sq += __shfl_xor_sync(0xffffffffu, sq, 16);
    sq += __shfl_xor_sync(0xffffffffu, sq, 8);
    sq += __shfl_xor_sync(0xffffffffu, sq, 4);
    sq += __shfl_xor_sync(0xffffffffu, sq, 2);
    sq += __shfl_xor_sync(0xffffffffu, sq, 1);
    if (lane == 0) red[w] = sq;
    __syncthreads();
    float tot = red[0] + red[1] + red[2] + red[3];
    // intra-norm; global L2 over 64 unit-norm rows is exactly sqrt(64)=8
    float inv = 0.125f / fmaxf(sqrtf(tot), EPS_);
    vlad_out[((size_t)n * K_ + k) * C_ + tid] = v * inv;
}

// ---------------- launch ----------------
extern "C" void kernel_launch(void* const* d_in, const int* in_sizes, int n_in,
                              void* d_out, int out_size) {
    const float* x    = (const float*)d_in[0];
    const float* W    = (const float*)d_in[1];
    const float* bias = (const float*)d_in[2];
    float* out        = (float*)d_out;
    float* vlad_out   = out;                               // [64, 8192]
    float* logits_out = out + (size_t)N_ * K_ * C_;        // [64, 64, 4096]

    static bool attr_set = false;
    if (!attr_set) {
        cudaFuncSetAttribute(kMega, cudaFuncAttributeMaxDynamicSharedMemorySize, SM_TOT);
        attr_set = true;
    }

    dim3 gM(4, N_);
    kMega<<<gM, 256, SM_TOT>>>(x, W, bias, logits_out);

    kD<<<N_ * K_, 128>>>(W, vlad_out);
}

// round 17
// speedup vs baseline: 1.0381x; 1.0381x over previous
#include <cuda_runtime.h>
#include <cuda_bf16.h>
#include <cstdint>
#include <math.h>

#define N_    64
#define C_    128
#define K_    64
#define P_    4096
#define ALPHA_ 50.0f
#define EPS_  1e-12f

typedef unsigned long long ull;
typedef unsigned int uint32;
typedef unsigned short ushort16;

// ---------------- scratch ----------------
__device__ float g_partial[N_ * 4 * K_ * C_];   // [n][ps][k][c]
__device__ float g_sasum[N_ * 4 * K_];          // [n][ps][k]

// ---------------- helpers ----------------
__device__ __forceinline__ uint32 smem_u32(const void* p) {
    uint32 a;
    asm("{ .reg .u64 t; cvta.to.shared.u64 t, %1; cvt.u32.u64 %0, t; }" : "=r"(a) : "l"(p));
    return a;
}
__device__ __forceinline__ void ldmat_x4(uint32& r0, uint32& r1, uint32& r2, uint32& r3, uint32 addr) {
    asm volatile("ldmatrix.sync.aligned.m8n8.x4.shared.b16 {%0,%1,%2,%3}, [%4];"
                 : "=r"(r0), "=r"(r1), "=r"(r2), "=r"(r3) : "r"(addr));
}
__device__ __forceinline__ void ldmat_x4t(uint32& r0, uint32& r1, uint32& r2, uint32& r3, uint32 addr) {
    asm volatile("ldmatrix.sync.aligned.m8n8.x4.trans.shared.b16 {%0,%1,%2,%3}, [%4];"
                 : "=r"(r0), "=r"(r1), "=r"(r2), "=r"(r3) : "r"(addr));
}
__device__ __forceinline__ void mma16816(float& d0, float& d1, float& d2, float& d3,
                                         uint32 a0, uint32 a1, uint32 a2, uint32 a3,
                                         uint32 b0, uint32 b1) {
    asm volatile("mma.sync.aligned.m16n8k16.row.col.f32.bf16.bf16.f32 "
                 "{%0,%1,%2,%3}, {%4,%5,%6,%7}, {%8,%9}, {%0,%1,%2,%3};"
                 : "+f"(d0), "+f"(d1), "+f"(d2), "+f"(d3)
                 : "r"(a0), "r"(a1), "r"(a2), "r"(a3), "r"(b0), "r"(b1));
}
__device__ __forceinline__ uint32 pack_bf16x2(float lo, float hi) {
    __nv_bfloat16 a = __float2bfloat16(lo), b = __float2bfloat16(hi);
    return (uint32)__bfloat16_as_ushort(a) | ((uint32)__bfloat16_as_ushort(b) << 16);
}
__device__ __forceinline__ void split_hl(float v, float& h, float& l) {
    __nv_bfloat16 hb = __float2bfloat16(v);
    h = __bfloat162float(hb);
    l = v - h;
}
// fast packed split: hw = {bf16(v1),bf16(v0)}, lw = residuals (cvt.rn everywhere)
__device__ __forceinline__ void cvt_pair(float v0, float v1, uint32& hw, uint32& lw) {
    asm("cvt.rn.bf16x2.f32 %0, %1, %2;" : "=r"(hw) : "f"(v1), "f"(v0));
    float h0 = __uint_as_float(hw << 16);
    float h1 = __uint_as_float(hw & 0xFFFF0000u);
    float l0 = v0 - h0, l1 = v1 - h1;
    asm("cvt.rn.bf16x2.f32 %0, %1, %2;" : "=r"(lw) : "f"(l1), "f"(l0));
}

// ---------------- smem layout (bytes) ----------------
#define SM_WNTH 0                 // WnT bf16 hi [64 k][128 c] rows 272B  17408
#define SM_WNTL 17408             // WnT bf16 lo                          17408
#define SM_XAH  34816             // x bf16 hi [128 c][64 p] rows 144B    18432
#define SM_XAL  53248             // x bf16 lo                            18432
#define SM_S    71680             // sas fp32 [64][68]                    17408
#define SM_SAH  89088             // sa bf16 hi [64 k][64 p] rows 144B     9216
#define SM_SAL  98304             // sa bf16 lo                            9216
#define SM_BS   107520
#define SM_INV  107776
#define SM_TOT  108032

#define SFS  68      // fp32 sas stride (floats)
#define BROW 144     // x/sa bf16 row stride (bytes)
#define WROW 272     // WnT bf16 row stride (bytes)

// ---------------- fused mega kernel: grid (4, 64), 256 threads ----------------
__global__ __launch_bounds__(256, 2) void kMega(const float* __restrict__ x,
                                                const float* __restrict__ W,
                                                const float* __restrict__ bias,
                                                float* __restrict__ logits_out) {
    extern __shared__ char smc[];
    float* sas  = (float*)(smc + SM_S);
    float* bs   = (float*)(smc + SM_BS);
    float* invv = (float*)(smc + SM_INV);

    const int tid = threadIdx.x;
    const int wid = tid >> 5;
    const int lane = tid & 31;
    const int n   = blockIdx.y;
    const int ps  = blockIdx.x;              // 0..3, 1024 px

    const uint32 sbase = smem_u32(smc);

    // ==== prologue: build WnT bf16 hi/lo [k][c] ====
    {
        float* wtmp = (float*)(smc + SM_XAH);   // fp32 [c][k] scratch (32KB)
        for (int i = tid; i < C_ * K_; i += 256) wtmp[i] = W[i];
        if (tid < 64) bs[tid] = bias[tid];
        __syncthreads();
        {
            const int kk = tid & 63, q = tid >> 6;
            float ss = 0.f;
            #pragma unroll 8
            for (int c = q * 32; c < q * 32 + 32; ++c) {
                float v = wtmp[c * K_ + kk];
                ss = fmaf(v, v, ss);
            }
            sas[q * 64 + kk] = ss;
        }
        __syncthreads();
        if (tid < 64) {
            float tot = sas[tid] + sas[64 + tid] + sas[128 + tid] + sas[192 + tid];
            sas[512 + tid] = 1.f / fmaxf(sqrtf(tot), EPS_);
        }
        __syncthreads();
        {
            const int kk = tid & 63, q = tid >> 6;
            float ik = sas[512 + kk];
            #pragma unroll
            for (int j = 0; j < 16; ++j) {
                int c0 = q * 32 + 2 * j;
                float v0 = wtmp[c0 * K_ + kk] * ik;
                float v1 = wtmp[(c0 + 1) * K_ + kk] * ik;
                float h0, l0, h1, l1;
                split_hl(v0, h0, l0);
                split_hl(v1, h1, l1);
                *(uint32*)(smc + SM_WNTH + kk * WROW + c0 * 2) = pack_bf16x2(h0, h1);
                *(uint32*)(smc + SM_WNTL + kk * WROW + c0 * 2) = pack_bf16x2(l0, l1);
            }
        }
        __syncthreads();
    }

    // role mappings
    const int pq = tid & 15, cq = tid >> 4;    // loader
    const int pN = tid >> 2, qN = tid & 3;     // softmax: pixel pN, k = qN+4i

    float acc[8][4];                           // GEMM2 accum (persistent)
    #pragma unroll
    for (int a = 0; a < 8; ++a)
        #pragma unroll
        for (int b = 0; b < 4; ++b) acc[a][b] = 0.f;
    float sasum16[16];
    #pragma unroll
    for (int i = 0; i < 16; ++i) sasum16[i] = 0.f;

    // hoist bias for this thread's fixed k-set (k = qN + 4i)
    float bs_r[16];
    #pragma unroll
    for (int i = 0; i < 16; ++i) bs_r[i] = bs[qN + 4 * i];

    const float* xbase = x + (size_t)n * C_ * P_ + ps * 1024;
    float* lb = logits_out + (size_t)n * K_ * P_ + ps * 1024;

    const int k0w = (wid & 3) * 16;            // GEMM1 warp tile
    const int phalf = (wid >> 2) * 32;

    for (int sub = 0; sub < 16; ++sub) {
        const int p0 = sub * 64;

        // ---- A: load gmem x -> bf16 hi/lo [c][p] + sumsq ----
        {
            const float* xp = xbase + p0 + pq * 4;
            float s0 = 0.f, s1 = 0.f, s2 = 0.f, s3 = 0.f;
            #pragma unroll
            for (int i = 0; i < 8; ++i) {
                int c = cq + 16 * i;
                float4 v = *(const float4*)(xp + (size_t)c * P_);
                s0 = fmaf(v.x, v.x, s0);
                s1 = fmaf(v.y, v.y, s1);
                s2 = fmaf(v.z, v.z, s2);
                s3 = fmaf(v.w, v.w, s3);
                uint2 hv, lv;
                cvt_pair(v.x, v.y, hv.x, lv.x);
                cvt_pair(v.z, v.w, hv.y, lv.y);
                *(uint2*)(smc + SM_XAH + c * BROW + pq * 8) = hv;
                *(uint2*)(smc + SM_XAL + c * BROW + pq * 8) = lv;
            }
            *(float4*)(sas + cq * 64 + pq * 4) = make_float4(s0, s1, s2, s3);
        }
        __syncthreads();   // (1)

        // ---- B: invn (tid<64) || GEMM1 tensor: D[k][p] = Wn^T x ----
        if (tid < 64) {
            float tot = 0.f;
            #pragma unroll
            for (int q = 0; q < 16; ++q) tot += sas[q * 64 + tid];
            invv[tid] = 1.f / fmaxf(sqrtf(tot), EPS_);
        }
        float f1[4][4];
        #pragma unroll
        for (int a = 0; a < 4; ++a)
            #pragma unroll
            for (int b = 0; b < 4; ++b) f1[a][b] = 0.f;
        {
            uint32 aH = sbase + SM_WNTH + (k0w + (lane & 15)) * WROW + (lane >> 4) * 16;
            uint32 aL = aH + (SM_WNTL - SM_WNTH);
            uint32 bB = sbase + SM_XAH + lane * BROW + phalf * 2;
            #pragma unroll
            for (int kcp = 0; kcp < 4; ++kcp) {
                uint32 AhA0, AhA1, AhA2, AhA3, AhB0, AhB1, AhB2, AhB3;
                uint32 AlA0, AlA1, AlA2, AlA3, AlB0, AlB1, AlB2, AlB3;
                ldmat_x4(AhA0, AhA1, AhA2, AhA3, aH + (2 * kcp) * 32);
                ldmat_x4(AhB0, AhB1, AhB2, AhB3, aH + (2 * kcp + 1) * 32);
                ldmat_x4(AlA0, AlA1, AlA2, AlA3, aL + (2 * kcp) * 32);
                ldmat_x4(AlB0, AlB1, AlB2, AlB3, aL + (2 * kcp + 1) * 32);
                #pragma unroll
                for (int nt = 0; nt < 4; ++nt) {
                    uint32 Bh0, Bh1, Bh2, Bh3, Bl0, Bl1, Bl2, Bl3;
                    uint32 ba = bB + kcp * 32 * BROW + nt * 16;
                    ldmat_x4t(Bh0, Bh1, Bh2, Bh3, ba);
                    ldmat_x4t(Bl0, Bl1, Bl2, Bl3, ba + (SM_XAL - SM_XAH));
                    mma16816(f1[nt][0], f1[nt][1], f1[nt][2], f1[nt][3],
                             AhA0, AhA1, AhA2, AhA3, Bh0, Bh1);
                    mma16816(f1[nt][0], f1[nt][1], f1[nt][2], f1[nt][3],
                             AhA0, AhA1, AhA2, AhA3, Bl0, Bl1);
                    mma16816(f1[nt][0], f1[nt][1], f1[nt][2], f1[nt][3],
                             AlA0, AlA1, AlA2, AlA3, Bh0, Bh1);
                    mma16816(f1[nt][0], f1[nt][1], f1[nt][2], f1[nt][3],
                             AhB0, AhB1, AhB2, AhB3, Bh2, Bh3);
                    mma16816(f1[nt][0], f1[nt][1], f1[nt][2], f1[nt][3],
                             AhB0, AhB1, AhB2, AhB3, Bl2, Bl3);
                    mma16816(f1[nt][0], f1[nt][1], f1[nt][2], f1[nt][3],
                             AlB0, AlB1, AlB2, AlB3, Bh2, Bh3);
                }
            }
        }
        __syncthreads();   // (2) invv ready; sas scratch free

        // ---- C: epilogue: x invn -> sas fp32 [k][p] AND logits -> gmem ----
        {
            const int r0 = k0w + (lane >> 2);
            #pragma unroll
            for (int nt = 0; nt < 4; ++nt) {
                int pc = phalf + nt * 8 + 2 * (lane & 3);
                float i0 = invv[pc], i1 = invv[pc + 1];
                float2 lo = make_float2(f1[nt][0] * i0, f1[nt][1] * i1);
                float2 hi = make_float2(f1[nt][2] * i0, f1[nt][3] * i1);
                *(float2*)(sas + r0 * SFS + pc)       = lo;
                *(float2*)(sas + (r0 + 8) * SFS + pc) = hi;
                *(float2*)(lb + (size_t)r0 * P_ + p0 + pc)       = lo;
                *(float2*)(lb + (size_t)(r0 + 8) * P_ + p0 + pc) = hi;
            }
        }
        __syncthreads();   // (3)

        // ---- E: softmax over k per pixel (4 thr/pixel), fused sa-bf16 store
        //         + in-register sasum accumulation ----
        {
            float lv[16];
            float m = -3.4e38f;
            #pragma unroll
            for (int i = 0; i < 16; ++i) {
                int k = qN + 4 * i;
                float t = (sas[k * SFS + pN] + bs_r[i]) * ALPHA_;
                lv[i] = t; m = fmaxf(m, t);
            }
            m = fmaxf(m, __shfl_xor_sync(0xffffffffu, m, 1));
            m = fmaxf(m, __shfl_xor_sync(0xffffffffu, m, 2));
            float s = 0.f;
            #pragma unroll
            for (int i = 0; i < 16; ++i) {
                float e = __expf(lv[i] - m);
                lv[i] = e; s += e;
            }
            s += __shfl_xor_sync(0xffffffffu, s, 1);
            s += __shfl_xor_sync(0xffffffffu, s, 2);
            float rs = 1.f / s;
            float iv = invv[pN];
            #pragma unroll
            for (int i = 0; i < 16; ++i) {
                float sa = lv[i] * rs;          // true sa (for sasum)
                sasum16[i] += sa;
                float v = sa * iv;              // invn-folded for GEMM2
                float h, l;
                split_hl(v, h, l);
                int k = qN + 4 * i;
                *(ushort16*)(smc + SM_SAH + k * BROW + pN * 2) =
                    __bfloat16_as_ushort(__float2bfloat16(h));
                *(ushort16*)(smc + SM_SAL + k * BROW + pN * 2) =
                    __bfloat16_as_ushort(__float2bfloat16(l));
            }
        }
        __syncthreads();   // (4) bf16 sa ready

        // ---- G: GEMM2 tensor: D[c][k] += x sa^T (contraction p) ----
        {
            const int c0 = wid * 16;
            const int ar = lane & 15, ah = lane >> 4;
            uint32 aAddrH = sbase + SM_XAH + (c0 + ar) * BROW + ah * 16;
            uint32 aAddrL = sbase + SM_XAL + (c0 + ar) * BROW + ah * 16;
            uint32 bRow = (lane >> 4) * 8 + (lane & 7);
            uint32 bHalf = ((lane >> 3) & 1) * 16;
            #pragma unroll
            for (int kc = 0; kc < 4; ++kc) {
                uint32 Ah0, Ah1, Ah2, Ah3, Al0, Al1, Al2, Al3;
                ldmat_x4(Ah0, Ah1, Ah2, Ah3, aAddrH + kc * 32);
                ldmat_x4(Al0, Al1, Al2, Al3, aAddrL + kc * 32);
                #pragma unroll
                for (int ntp = 0; ntp < 4; ++ntp) {
                    uint32 Bh0, Bh1, Bh2, Bh3, Bl0, Bl1, Bl2, Bl3;
                    uint32 baH = sbase + SM_SAH + (ntp * 16 + bRow) * BROW + bHalf + kc * 32;
                    uint32 baL = baH + (SM_SAL - SM_SAH);
                    ldmat_x4(Bh0, Bh1, Bh2, Bh3, baH);
                    ldmat_x4(Bl0, Bl1, Bl2, Bl3, baL);
                    int ntA = 2 * ntp, ntB = 2 * ntp + 1;
                    mma16816(acc[ntA][0], acc[ntA][1], acc[ntA][2], acc[ntA][3],
                             Ah0, Ah1, Ah2, Ah3, Bh0, Bh1);
                    mma16816(acc[ntA][0], acc[ntA][1], acc[ntA][2], acc[ntA][3],
                             Ah0, Ah1, Ah2, Ah3, Bl0, Bl1);
                    mma16816(acc[ntA][0], acc[ntA][1], acc[ntA][2], acc[ntA][3],
                             Al0, Al1, Al2, Al3, Bh0, Bh1);
                    mma16816(acc[ntB][0], acc[ntB][1], acc[ntB][2], acc[ntB][3],
                             Ah0, Ah1, Ah2, Ah3, Bh2, Bh3);
                    mma16816(acc[ntB][0], acc[ntB][1], acc[ntB][2], acc[ntB][3],
                             Ah0, Ah1, Ah2, Ah3, Bl2, Bl3);
                    mma16816(acc[ntB][0], acc[ntB][1], acc[ntB][2], acc[ntB][3],
                             Al0, Al1, Al2, Al3, Bh2, Bh3);
                }
            }
        }
        __syncthreads();   // (5) mma reads done before next A overwrites
    }

    // ---- epilogue: write acc -> g_partial [k][c] ----
    {
        float* pp = g_partial + ((size_t)(n * 4 + ps) * K_) * C_;
        const int row = wid * 16 + (lane >> 2);
        const int col = 2 * (lane & 3);
        #pragma unroll
        for (int nt = 0; nt < 8; ++nt) {
            int k0 = nt * 8 + col;
            pp[(k0    ) * C_ + row    ] = acc[nt][0];
            pp[(k0 + 1) * C_ + row    ] = acc[nt][1];
            pp[(k0    ) * C_ + row + 8] = acc[nt][2];
            pp[(k0 + 1) * C_ + row + 8] = acc[nt][3];
        }
    }

    // ---- sasum: in-warp pixel reduce, then cross-warp via smem ----
    #pragma unroll
    for (int i = 0; i < 16; ++i) {
        float s = sasum16[i];
        s += __shfl_xor_sync(0xffffffffu, s, 4);
        s += __shfl_xor_sync(0xffffffffu, s, 8);
        s += __shfl_xor_sync(0xffffffffu, s, 16);
        if (lane < 4) sas[wid * 64 + lane + 4 * i] = s;   // k = lane + 4i
    }
    __syncthreads();
    if (tid < 64) {
        float t = 0.f;
        #pragma unroll
        for (int q = 0; q < 8; ++q) t += sas[q * 64 + tid];
        g_sasum[(n * 4 + ps) * 64 + tid] = t;
    }
}

// ---------------- kernel D: combine + subtract + intra-norm + global/8 ----------------
__global__ __launch_bounds__(128) void kD(const float* __restrict__ W,
                                          float* __restrict__ vlad_out) {
    __shared__ float red[4];
    const int b = blockIdx.x;
    const int n = b >> 6, k = b & 63, tid = threadIdx.x;
    const int lane = tid & 31, w = tid >> 5;

    float sasum = 0.f;
    #pragma unroll
    for (int ps = 0; ps < 4; ++ps) sasum += g_sasum[(n * 4 + ps) * 64 + k];

    float v = 0.f;
    #pragma unroll
    for (int ps = 0; ps < 4; ++ps)
        v += g_partial[((size_t)(n * 4 + ps) * K_ + k) * C_ + tid];
    v = fmaf(-sasum, W[tid * K_ + k], v);

    float sq = v * v;
    sq += __shfl_xor_sync(0xffffffffu, sq, 16);
    sq += __shfl_xor_sync(0xffffffffu, sq, 8);
    sq += __shfl_xor_sync(0xffffffffu, sq, 4);
    sq += __shfl_xor_sync(0xffffffffu, sq, 2);
    sq += __shfl_xor_sync(0xffffffffu, sq, 1);
    if (lane == 0) red[w] = sq;
    __syncthreads();
    float tot = red[0] + red[1] + red[2] + red[3];
    // intra-norm; global L2 over 64 unit-norm rows is exactly sqrt(64)=8
    float inv = 0.125f / fmaxf(sqrtf(tot), EPS_);
    vlad_out[((size_t)n * K_ + k) * C_ + tid] = v * inv;
}

// ---------------- launch ----------------
extern "C" void kernel_launch(void* const* d_in, const int* in_sizes, int n_in,
                              void* d_out, int out_size) {
    const float* x    = (const float*)d_in[0];
    const float* W    = (const float*)d_in[1];
    const float* bias = (const float*)d_in[2];
    float* out        = (float*)d_out;
    float* vlad_out   = out;                               // [64, 8192]
    float* logits_out = out + (size_t)N_ * K_ * C_;        // [64, 64, 4096]

    static bool attr_set = false;
    if (!attr_set) {
        cudaFuncSetAttribute(kMega, cudaFuncAttributeMaxDynamicSharedMemorySize, SM_TOT);
        attr_set = true;
    }

    dim3 gM(4, N_);
    kMega<<<gM, 256, SM_TOT>>>(x, W, bias, logits_out);

    kD<<<N_ * K_, 128>>>(W, vlad_out);
}